// round 14
// baseline (speedup 1.0000x reference)
#include <cuda_runtime.h>
#include <cuda.h>
#include <cstdint>

// Problem constants
#define BB 8
#define TT 128
#define DD 1024
#define VV 4096
#define RR 16
#define HH 2
#define GG (VV * RR * HH)  // 131072 rows of W
#define NU 2048            // work units of 64 rows
#define NCTA 444           // persistent CTAs, 3 per SM
#define STAGES 4           // ring stages (8KB each)
#define STAGE_BYTES 8192   // 64 rows x 32 cols x 4B
#define LOOKAHEAD 3

// Dynamic smem layout (bytes) — shared by both kernels
#define SM_W 0                          // 4 x 8KB W tiles
#define SM_HS 32768                     // 8192 floats: swizzled h_last
#define SM_SBLK 65536                   // 256 floats: CTA-local S [h][r*8+b]
#define SM_SPTS 66560                   // 16 ints: points
#define SM_MISC 66624                   // tickets + last flag
#define SM_MBAR 66688                   // full[4] at +s*8 (TMA kernel only)
#define SMEM_TOTAL 66816

typedef unsigned long long ull;

// Scratch (device globals — no allocation allowed)
__device__ float g_S[256];       // [h][r*8+b] sums of exp (reset by last CTA each run)
__device__ float g_E[256];       // [b][h][r] selected-row exps (all slots rewritten every run)
__device__ unsigned g_tick = 0;  // work ticket counter (reset by last CTA)
__device__ unsigned g_fin = 0;   // finished-CTA counter (reset by last CTA)
__device__ __align__(128) ull g_tmap[16];  // tensormap in GLOBAL memory (test_tma pattern)

__device__ __forceinline__ void fma2(ull& d, ull a, ull b) {
    asm("fma.rn.f32x2 %0, %1, %2, %0;" : "+l"(d) : "l"(a), "l"(b));
}
__device__ __forceinline__ ull packw(float f) {
    ull r;
    asm("mov.b64 %0, {%1, %1};" : "=l"(r) : "r"(__float_as_uint(f)));
    return r;
}
__device__ __forceinline__ float lo32(ull a) { return __uint_as_float((unsigned)a); }
__device__ __forceinline__ float hi32(ull a) { return __uint_as_float((unsigned)(a >> 32)); }

// ---- mbarrier / TMA primitives (strings identical to ptx_helpers.cuh) ----
__device__ __forceinline__ void mbar_init(uint32_t mbar, uint32_t count) {
    asm volatile("mbarrier.init.shared.b64 [%0], %1;" :: "r"(mbar), "r"(count) : "memory");
}
__device__ __forceinline__ void mbar_expect_tx(uint32_t mbar, uint32_t bytes) {
    asm volatile("mbarrier.arrive.expect_tx.shared.b64 _, [%0], %1;"
                 :: "r"(mbar), "r"(bytes) : "memory");
}
__device__ __forceinline__ void mbar_wait(uint32_t mbar, int parity) {
    asm volatile(
        "{\n\t"
        ".reg .pred P;\n\t"
        "LW_%=:\n\t"
        "mbarrier.try_wait.parity.acquire.cta.shared::cta.b64 P, [%0], %1, 0x989680;\n\t"
        "@P bra LD_%=;\n\t"
        "bra LW_%=;\n\t"
        "LD_%=:\n\t"
        "}"
        :: "r"(mbar), "r"(parity) : "memory");
}
__device__ __forceinline__ void tma2d(uint32_t dst, const void* tm,
                                      int col, int row, uint32_t mbar) {
    asm volatile(
        "cp.async.bulk.tensor.2d.shared::cta.global.tile.mbarrier::complete_tx::bytes "
        "[%0], [%1, {%2, %3}], [%4];"
        :: "r"(dst), "l"(tm), "r"(col), "r"(row), "r"(mbar) : "memory");
}

// ---- cp.async primitives (fallback kernel) ----
__device__ __forceinline__ void cp16(uint32_t dst, const float* src) {
    asm volatile("cp.async.cg.shared.global [%0], [%1], 16;" :: "r"(dst), "l"(src) : "memory");
}
__device__ __forceinline__ void cp_commit() {
    asm volatile("cp.async.commit_group;" ::: "memory");
}
__device__ __forceinline__ void cp_wait2() {
    asm volatile("cp.async.wait_group 2;" ::: "memory");
}
__device__ __forceinline__ void cp_waitall() {
    asm volatile("cp.async.wait_all;" ::: "memory");
}

// Reduce-scatter across the 8-lane c-group: on entry s[b] = lane-partial for batch b;
// on exit lane c holds the full (8-lane) sum for batch c. 7 shuffles.
__device__ __forceinline__ float rscatter8(const float s[8], int c) {
    bool b4 = (c & 4) != 0;
    float kp[4], snd[4];
#pragma unroll
    for (int i = 0; i < 4; i++) { snd[i] = b4 ? s[i] : s[i + 4]; kp[i] = b4 ? s[i + 4] : s[i]; }
#pragma unroll
    for (int i = 0; i < 4; i++) kp[i] += __shfl_xor_sync(0xffffffffu, snd[i], 4);
    bool b2 = (c & 2) != 0;
    float k2[2], s2[2];
#pragma unroll
    for (int i = 0; i < 2; i++) { s2[i] = b2 ? kp[i] : kp[i + 2]; k2[i] = b2 ? kp[i + 2] : kp[i]; }
#pragma unroll
    for (int i = 0; i < 2; i++) k2[i] += __shfl_xor_sync(0xffffffffu, s2[i], 2);
    bool b1 = (c & 1) != 0;
    float s1 = b1 ? k2[0] : k2[1];
    float k1 = b1 ? k2[1] : k2[0];
    return k1 + __shfl_xor_sync(0xffffffffu, s1, 1);
}

// Copy the tensormap (by-value launch param) into global memory.
__global__ void k_setup(const __grid_constant__ CUtensorMap tm) {
    const ull* s = (const ull*)&tm;
    if (threadIdx.x < 16) g_tmap[threadIdx.x] = s[threadIdx.x];
}

// ============================ TMA main kernel ============================
// Persistent: 444 CTAs x 256 threads (3/SM). 64-row units via global tickets.
// W: 4-stage TMA ring — ONE bulk tensor load per 8KB tile per CTA (zero LSU
// wavefronts for fills). Protocol: FULL barriers only (count=1, expect_tx by
// tid 0); one __syncthreads per tile; produce tile k+3 after the sync retiring
// tile k, so its stage (holding tile k-1) is provably free. Producer never
// waits — no producer deadlock possible. Tiles land row-major (128B rows):
// warp LDS.128 reads contiguous 512B, conflict-free, no W swizzle.
// h in smem, XOR-swizzled; the swizzle term reduces to XOR with c.
__global__ void __launch_bounds__(256, 3) k_main(const float* __restrict__ lhs,
                                                 const float* __restrict__ bias,
                                                 const void* __restrict__ pts_raw,
                                                 float* __restrict__ out) {
    extern __shared__ __align__(128) char smem[];
    float* hs = (float*)(smem + SM_HS);
    float* sblk = (float*)(smem + SM_SBLK);
    int* spts = (int*)(smem + SM_SPTS);
    int* misc = (int*)(smem + SM_MISC);  // [0]=cur ticket, [1]=next ticket, [2]=last flag

    const int tid = threadIdx.x;
    const int warp = tid >> 5, lane = tid & 31;
    const int rgrp = lane >> 3, c = lane & 7;

    const uint32_t smem_u32 = (uint32_t)__cvta_generic_to_shared(smem);
    const uint32_t mb_full = smem_u32 + SM_MBAR;
    // This thread's read slot within a stage: row_local = warp*8 + q*4 + rgrp,
    // byte = row_local*128 + c*16  (q term = +512)
    const uint32_t rslot = smem_u32 + SM_W + warp * 1024 + rgrp * 128 + c * 16;
    const void* tmp = (const void*)g_tmap;

    if (tid == 0) {
#pragma unroll
        for (int s = 0; s < STAGES; s++) mbar_init(mb_full + s * 8, 1);
        asm volatile("fence.proxy.async.shared::cta;" ::: "memory");
        misc[0] = (int)atomicAdd(&g_tick, 1u);
        misc[1] = (int)atomicAdd(&g_tick, 1u);
    }

    if (tid < 16) {
        // Detect int64 vs int32 points: values < 4096, so int64 data has all-zero hi words.
        const ull* pw = (const ull*)pts_raw;
        ull h = 0;
#pragma unroll
        for (int i = 0; i < 8; i++) h |= (pw[i] >> 32);
        bool is64 = (h == 0ULL);
        spts[tid] = is64 ? (int)((const long long*)pts_raw)[tid]
                         : ((const int*)pts_raw)[tid];
    }
    sblk[tid] = 0.f;

    // Stage h_last[b][k] = lhs[b, T-1, k] with XOR swizzle on 16B chunks.
#pragma unroll
    for (int i = 0; i < 32; i++) {
        int idx = tid + i * 256;
        int b = idx >> 10, k = idx & 1023;
        int idx16 = k * 2 + (b >> 2);
        int s = idx16 ^ ((idx16 >> 3) & 7);
        hs[s * 4 + (b & 3)] = lhs[b * (TT * DD) + (TT - 1) * DD + k];
    }
    __syncthreads();  // mbarriers + fence + tickets + h visible

    int cur = misc[0];
    int nxt = misc[1];

    const ulonglong2* h8 = (const ulonglong2*)hs;
    int pcnt = 0, ccnt = 0;

    // Prologue: produce tiles 0..2 of cur into stages 0..2
    if (cur < NU) {
        if (tid == 0) {
#pragma unroll
            for (int t = 0; t < LOOKAHEAD; t++) {
                mbar_expect_tx(mb_full + t * 8, STAGE_BYTES);
                tma2d(smem_u32 + SM_W + t * STAGE_BYTES, tmp, t * 32, cur * 64,
                      mb_full + t * 8);
            }
        }
        pcnt = LOOKAHEAD;
    }

    while (cur < NU) {
        ull acc[2][4] = {};

        for (int t = 0; t < 32; t++) {
            // Consume tile (global index ccnt)
            int s = ccnt & 3;
            int pc = (ccnt >> 2) & 1;
            ccnt++;
            mbar_wait(mb_full + s * 8, pc);

            uint32_t rb = rslot + s * STAGE_BYTES;
            float4 w[2];
            asm volatile("ld.shared.v4.f32 {%0,%1,%2,%3}, [%4];"
                         : "=f"(w[0].x), "=f"(w[0].y), "=f"(w[0].z), "=f"(w[0].w)
                         : "r"(rb));
            asm volatile("ld.shared.v4.f32 {%0,%1,%2,%3}, [%4];"
                         : "=f"(w[1].x), "=f"(w[1].y), "=f"(w[1].z), "=f"(w[1].w)
                         : "r"(rb + 512));

            // h addresses: base has low-3 bits clear; swizzle reduces to XOR with c.
            const ulonglong2* hb = h8 + t * 64 + c * 8;
#define STEP(comp, kk)                                                        \
    do {                                                                      \
        ulonglong2 hA = hb[(2 * (kk)) ^ c];     /* batches 0-3 */             \
        ulonglong2 hB = hb[(2 * (kk) + 1) ^ c]; /* batches 4-7 */             \
        ull wd0 = packw(w[0].comp);                                           \
        fma2(acc[0][0], wd0, hA.x); fma2(acc[0][1], wd0, hA.y);               \
        fma2(acc[0][2], wd0, hB.x); fma2(acc[0][3], wd0, hB.y);               \
        ull wd1 = packw(w[1].comp);                                           \
        fma2(acc[1][0], wd1, hA.x); fma2(acc[1][1], wd1, hA.y);               \
        fma2(acc[1][2], wd1, hB.x); fma2(acc[1][3], wd1, hB.y);               \
    } while (0)
            STEP(x, 0);
            STEP(y, 1);
            STEP(z, 2);
            STEP(w, 3);
#undef STEP

            __syncthreads();  // tile fully consumed by ALL warps -> old stage reusable

            // Produce lookahead tile into the stage freed one iteration ago
            int ft = t + LOOKAHEAD;
            int punit = (ft < 32) ? cur : nxt;
            int ptile = (ft < 32) ? ft : ft - 32;
            if (punit < NU) {
                if (tid == 0) {
                    int ps = pcnt & 3;
                    mbar_expect_tx(mb_full + ps * 8, STAGE_BYTES);
                    tma2d(smem_u32 + SM_W + ps * STAGE_BYTES, tmp, ptile * 32,
                          punit * 64, mb_full + ps * 8);
                }
                pcnt++;
            }
        }

        // Unit epilogue: reduce-scatter (lane c ends with batch c), exp, accumulate.
        int hidx = cur >> 10;  // (cur*64) >> 16
#pragma unroll
        for (int q = 0; q < 2; q++) {
            float s[8];
#pragma unroll
            for (int p = 0; p < 4; p++) {
                s[2 * p] = lo32(acc[q][p]);
                s[2 * p + 1] = hi32(acc[q][p]);
            }
            float tot = rscatter8(s, c);
            int g = cur * 64 + warp * 8 + q * 4 + rgrp;
            float ev = expf(tot + __ldg(&bias[g]));
            int r = g & (RR - 1);
            atomicAdd(&sblk[hidx * 128 + r * 8 + c], ev);
            int v = (g >> 4) & (VV - 1);
            if (v == spts[c * 2 + hidx]) g_E[c * 32 + hidx * 16 + r] = ev;
        }

        // Advance: cur <- nxt (its early tiles are already in the ring), grab a new nxt.
        cur = nxt;
        if (cur < NU) {
            if (tid == 0) misc[1] = (int)atomicAdd(&g_tick, 1u);
            __syncthreads();
            nxt = misc[1];
        }
    }

    __syncthreads(); // all unit epilogues' sblk atomics done
    atomicAdd(&g_S[tid], sblk[tid]);  // tid in [0,256): one red per slot per CTA
    __threadfence();
    __syncthreads();
    if (tid == 0) {
        unsigned o = atomicAdd(&g_fin, 1u);
        misc[2] = (o == (unsigned)(NCTA - 1));
    }
    __syncthreads();

    if (misc[2]) {
        __threadfence();  // acquire: all CTAs' g_S reds visible
        if (tid < 8) {
            float n = 0.f, p = 0.f;
#pragma unroll
            for (int rr = 0; rr < 16; rr++) {
                n += g_S[rr * 8 + tid] * g_S[128 + rr * 8 + tid];
                p += g_E[tid * 32 + rr] * g_E[tid * 32 + 16 + rr];
            }
            out[tid] = p;       // p_eval
            out[8 + tid] = n;   // norm_const
        }
        __syncthreads();  // outputs written before scratch reset
        g_S[tid] = 0.f;   // reset for next graph replay
        if (tid == 0) { g_tick = 0; g_fin = 0; }
    }
}

// ====================== Fallback: proven cp.async kernel ======================
__global__ void __launch_bounds__(256, 3) k_fb(const float* __restrict__ lhs,
                                               const float* __restrict__ Wm,
                                               const float* __restrict__ bias,
                                               const void* __restrict__ pts_raw,
                                               float* __restrict__ out) {
    extern __shared__ __align__(128) char smem[];
    float* hs = (float*)(smem + SM_HS);
    float* sblk = (float*)(smem + SM_SBLK);
    int* spts = (int*)(smem + SM_SPTS);
    int* misc = (int*)(smem + SM_MISC);

    const int tid = threadIdx.x;
    const int warp = tid >> 5, lane = tid & 31;
    const int rgrp = lane >> 3, c = lane & 7;

    const uint32_t smem_u32 = (uint32_t)__cvta_generic_to_shared(smem);
    const uint32_t wbase = smem_u32 + SM_W + warp * 1024 + lane * 16;

    if (tid < 16) {
        const ull* pw = (const ull*)pts_raw;
        ull h = 0;
#pragma unroll
        for (int i = 0; i < 8; i++) h |= (pw[i] >> 32);
        bool is64 = (h == 0ULL);
        spts[tid] = is64 ? (int)((const long long*)pts_raw)[tid]
                         : ((const int*)pts_raw)[tid];
    }
    sblk[tid] = 0.f;

#pragma unroll
    for (int i = 0; i < 32; i++) {
        int idx = tid + i * 256;
        int b = idx >> 10, k = idx & 1023;
        int idx16 = k * 2 + (b >> 2);
        int s = idx16 ^ ((idx16 >> 3) & 7);
        hs[s * 4 + (b & 3)] = lhs[b * (TT * DD) + (TT - 1) * DD + k];
    }

    if (tid == 0) {
        misc[0] = (int)atomicAdd(&g_tick, 1u);
        misc[1] = (int)atomicAdd(&g_tick, 1u);
    }
    __syncthreads();
    int cur = misc[0];
    int nxt = misc[1];

    const ulonglong2* h8 = (const ulonglong2*)hs;
    int swrite = STAGES - 1, sread = 0;

    if (cur < NU) {
        const float* g0 = Wm + (size_t)(cur * 64 + warp * 8 + rgrp) * 1024 + c * 4;
#pragma unroll
        for (int t = 0; t < STAGES - 1; t++) {
            uint32_t d = wbase + t * STAGE_BYTES;
            cp16(d, g0 + t * 32);
            cp16(d + 512, g0 + 4096 + t * 32);
            cp_commit();
        }
    } else {
#pragma unroll
        for (int t = 0; t < STAGES - 1; t++) cp_commit();
    }

    while (cur < NU) {
        const float* gc = Wm + (size_t)(cur * 64 + warp * 8 + rgrp) * 1024 + c * 4;
        const float* gn = (nxt < NU)
                              ? Wm + (size_t)(nxt * 64 + warp * 8 + rgrp) * 1024 + c * 4
                              : (const float*)0;

        ull acc[2][4] = {};

        for (int t = 0; t < 32; t++) {
            cp_wait2();
            {
                int ft = t + (STAGES - 1);
                uint32_t d = wbase + swrite * STAGE_BYTES;
                if (ft < 32) {
                    cp16(d, gc + ft * 32);
                    cp16(d + 512, gc + 4096 + ft * 32);
                } else if (gn) {
                    int f2 = ft - 32;
                    cp16(d, gn + f2 * 32);
                    cp16(d + 512, gn + 4096 + f2 * 32);
                }
                cp_commit();
                swrite++; if (swrite == STAGES) swrite = 0;
            }

            uint32_t s = wbase + sread * STAGE_BYTES;
            sread++; if (sread == STAGES) sread = 0;
            float4 w[2];
            asm volatile("ld.shared.v4.f32 {%0,%1,%2,%3}, [%4];"
                         : "=f"(w[0].x), "=f"(w[0].y), "=f"(w[0].z), "=f"(w[0].w)
                         : "r"(s));
            asm volatile("ld.shared.v4.f32 {%0,%1,%2,%3}, [%4];"
                         : "=f"(w[1].x), "=f"(w[1].y), "=f"(w[1].z), "=f"(w[1].w)
                         : "r"(s + 512));

            const ulonglong2* hb = h8 + t * 64 + c * 8;
#define STEP(comp, kk)                                                        \
    do {                                                                      \
        ulonglong2 hA = hb[(2 * (kk)) ^ c];                                   \
        ulonglong2 hB = hb[(2 * (kk) + 1) ^ c];                               \
        ull wd0 = packw(w[0].comp);                                           \
        fma2(acc[0][0], wd0, hA.x); fma2(acc[0][1], wd0, hA.y);               \
        fma2(acc[0][2], wd0, hB.x); fma2(acc[0][3], wd0, hB.y);               \
        ull wd1 = packw(w[1].comp);                                           \
        fma2(acc[1][0], wd1, hA.x); fma2(acc[1][1], wd1, hA.y);               \
        fma2(acc[1][2], wd1, hB.x); fma2(acc[1][3], wd1, hB.y);               \
    } while (0)
            STEP(x, 0);
            STEP(y, 1);
            STEP(z, 2);
            STEP(w, 3);
#undef STEP
        }

        int hidx = cur >> 10;
#pragma unroll
        for (int q = 0; q < 2; q++) {
            float s[8];
#pragma unroll
            for (int p = 0; p < 4; p++) {
                s[2 * p] = lo32(acc[q][p]);
                s[2 * p + 1] = hi32(acc[q][p]);
            }
            float tot = rscatter8(s, c);
            int g = cur * 64 + warp * 8 + q * 4 + rgrp;
            float ev = expf(tot + __ldg(&bias[g]));
            int r = g & (RR - 1);
            atomicAdd(&sblk[hidx * 128 + r * 8 + c], ev);
            int v = (g >> 4) & (VV - 1);
            if (v == spts[c * 2 + hidx]) g_E[c * 32 + hidx * 16 + r] = ev;
        }

        cur = nxt;
        if (cur < NU) {
            if (tid == 0) misc[1] = (int)atomicAdd(&g_tick, 1u);
            __syncthreads();
            nxt = misc[1];
        }
    }

    cp_waitall();
    __syncthreads();
    atomicAdd(&g_S[tid], sblk[tid]);
    __threadfence();
    __syncthreads();
    if (tid == 0) {
        unsigned o = atomicAdd(&g_fin, 1u);
        misc[2] = (o == (unsigned)(NCTA - 1));
    }
    __syncthreads();

    if (misc[2]) {
        __threadfence();
        if (tid < 8) {
            float n = 0.f, p = 0.f;
#pragma unroll
            for (int rr = 0; rr < 16; rr++) {
                n += g_S[rr * 8 + tid] * g_S[128 + rr * 8 + tid];
                p += g_E[tid * 32 + rr] * g_E[tid * 32 + 16 + rr];
            }
            out[tid] = p;
            out[8 + tid] = n;
        }
        __syncthreads();
        g_S[tid] = 0.f;
        if (tid == 0) { g_tick = 0; g_fin = 0; }
    }
}

// ---- Host side ----
typedef CUresult (*tmap_encode_fn)(CUtensorMap*, CUtensorMapDataType, cuuint32_t, void*,
                                   const cuuint64_t*, const cuuint64_t*, const cuuint32_t*,
                                   const cuuint32_t*, CUtensorMapInterleave, CUtensorMapSwizzle,
                                   CUtensorMapL2promotion, CUtensorMapFloatOOBfill);

extern "C" void kernel_launch(void* const* d_in, const int* in_sizes, int n_in,
                              void* d_out, int out_size) {
    const float* lhs = nullptr;
    const float* Wm = nullptr;
    const float* bias = nullptr;
    const void* pts = nullptr;
    for (int i = 0; i < n_in; i++) {
        int sz = in_sizes[i];
        if (sz == GG * DD) Wm = (const float*)d_in[i];
        else if (sz == BB * TT * DD) lhs = (const float*)d_in[i];
        else if (sz == GG) bias = (const float*)d_in[i];
        else if (sz == BB * HH) pts = d_in[i];
    }
    if (!lhs) lhs = (const float*)d_in[0];
    if (!Wm) Wm = (const float*)d_in[1];
    if (!bias) bias = (const float*)d_in[2];
    if (!pts) pts = d_in[3];

    static int mode = -1;  // 0 = TMA path, 1 = cp.async fallback
    static CUtensorMap tmap;
    if (mode < 0) {
        mode = 1;
        void* p = nullptr;
        cudaDriverEntryPointQueryResult qr = cudaDriverEntryPointSymbolNotFound;
        cudaError_t ce = cudaGetDriverEntryPointByVersion("cuTensorMapEncodeTiled", &p,
                                                          12000, cudaEnableDefault, &qr);
        if (ce == cudaSuccess && p && qr == cudaDriverEntryPointSuccess) {
            tmap_encode_fn tfn = (tmap_encode_fn)p;
            cuuint64_t dims[2] = {(cuuint64_t)DD, (cuuint64_t)GG};
            cuuint64_t strides[1] = {(cuuint64_t)DD * sizeof(float)};
            cuuint32_t box[2] = {32, 64};
            cuuint32_t estr[2] = {1, 1};
            CUresult cr = tfn(&tmap, CU_TENSOR_MAP_DATA_TYPE_FLOAT32, 2, (void*)Wm, dims,
                              strides, box, estr, CU_TENSOR_MAP_INTERLEAVE_NONE,
                              CU_TENSOR_MAP_SWIZZLE_NONE, CU_TENSOR_MAP_L2_PROMOTION_L2_128B,
                              CU_TENSOR_MAP_FLOAT_OOB_FILL_NONE);
            if (cr == CUDA_SUCCESS) mode = 0;
        }
        cudaFuncSetAttribute(k_main, cudaFuncAttributeMaxDynamicSharedMemorySize, SMEM_TOTAL);
        cudaFuncSetAttribute(k_fb, cudaFuncAttributeMaxDynamicSharedMemorySize, SMEM_TOTAL);
    }

    if (mode == 0) {
        k_setup<<<1, 16>>>(tmap);
        k_main<<<NCTA, 256, SMEM_TOTAL>>>(lhs, bias, pts, (float*)d_out);
    } else {
        k_fb<<<NCTA, 256, SMEM_TOTAL>>>(lhs, Wm, bias, pts, (float*)d_out);
    }
}

// round 16
// speedup vs baseline: 1.1034x; 1.1034x over previous
#include <cuda_runtime.h>
#include <cuda.h>
#include <cstdint>

// Problem constants
#define BB 8
#define TT 128
#define DD 1024
#define VV 4096
#define RR 16
#define HH 2
#define GG (VV * RR * HH)  // 131072 rows of W
#define NU 2048            // work units of 64 rows
#define NCTA 444           // persistent CTAs, 3 per SM
#define PAIR_BYTES 16384   // 64 rows x 64 cols x 4B (two k-tiles, one TMA)

// Dynamic smem layout (bytes) — shared by both kernels
#define SM_W 0                          // 2 x 16KB W pair-buffers (256B rows)
#define SM_HS 32768                     // 8192 floats: swizzled h_last
#define SM_SBLK 65536                   // 256 floats: CTA-local S [h][r*8+b]
#define SM_SPTS 66560                   // 16 ints: points
#define SM_MISC 66624                   // tickets + last flag
#define SM_MBAR 66688                   // full[2] at +buf*8
#define SMEM_TOTAL 66816

typedef unsigned long long ull;

// Scratch (device globals — no allocation allowed)
__device__ float g_S[256];       // [h][r*8+b] sums of exp (reset by last CTA each run)
__device__ float g_E[256];       // [b][h][r] selected-row exps (all slots rewritten every run)
__device__ unsigned g_tick = 0;  // work ticket counter (reset by last CTA)
__device__ unsigned g_fin = 0;   // finished-CTA counter (reset by last CTA)
__device__ __align__(128) ull g_tmap[16];  // tensormap in GLOBAL memory

__device__ __forceinline__ void fma2(ull& d, ull a, ull b) {
    asm("fma.rn.f32x2 %0, %1, %2, %0;" : "+l"(d) : "l"(a), "l"(b));
}
__device__ __forceinline__ ull packw(float f) {
    ull r;
    asm("mov.b64 %0, {%1, %1};" : "=l"(r) : "r"(__float_as_uint(f)));
    return r;
}
__device__ __forceinline__ float lo32(ull a) { return __uint_as_float((unsigned)a); }
__device__ __forceinline__ float hi32(ull a) { return __uint_as_float((unsigned)(a >> 32)); }

// ---- mbarrier / TMA primitives ----
__device__ __forceinline__ void mbar_init(uint32_t mbar, uint32_t count) {
    asm volatile("mbarrier.init.shared.b64 [%0], %1;" :: "r"(mbar), "r"(count) : "memory");
}
__device__ __forceinline__ void mbar_expect_tx(uint32_t mbar, uint32_t bytes) {
    asm volatile("mbarrier.arrive.expect_tx.shared.b64 _, [%0], %1;"
                 :: "r"(mbar), "r"(bytes) : "memory");
}
__device__ __forceinline__ void mbar_wait(uint32_t mbar, int parity) {
    asm volatile(
        "{\n\t"
        ".reg .pred P;\n\t"
        "LW_%=:\n\t"
        "mbarrier.try_wait.parity.acquire.cta.shared::cta.b64 P, [%0], %1, 0x989680;\n\t"
        "@P bra LD_%=;\n\t"
        "bra LW_%=;\n\t"
        "LD_%=:\n\t"
        "}"
        :: "r"(mbar), "r"(parity) : "memory");
}
__device__ __forceinline__ void tma2d(uint32_t dst, const void* tm,
                                      int col, int row, uint32_t mbar) {
    asm volatile(
        "cp.async.bulk.tensor.2d.shared::cta.global.tile.mbarrier::complete_tx::bytes "
        "[%0], [%1, {%2, %3}], [%4];"
        :: "r"(dst), "l"(tm), "r"(col), "r"(row), "r"(mbar) : "memory");
}

// ---- cp.async primitives (fallback kernel) ----
__device__ __forceinline__ void cp16(uint32_t dst, const float* src) {
    asm volatile("cp.async.cg.shared.global [%0], [%1], 16;" :: "r"(dst), "l"(src) : "memory");
}
__device__ __forceinline__ void cp_commit() {
    asm volatile("cp.async.commit_group;" ::: "memory");
}
__device__ __forceinline__ void cp_wait2() {
    asm volatile("cp.async.wait_group 2;" ::: "memory");
}
__device__ __forceinline__ void cp_waitall() {
    asm volatile("cp.async.wait_all;" ::: "memory");
}

// Reduce-scatter across the 8-lane c-group: on entry s[b] = lane-partial for batch b;
// on exit lane c holds the full (8-lane) sum for batch c. 7 shuffles.
__device__ __forceinline__ float rscatter8(const float s[8], int c) {
    bool b4 = (c & 4) != 0;
    float kp[4], snd[4];
#pragma unroll
    for (int i = 0; i < 4; i++) { snd[i] = b4 ? s[i] : s[i + 4]; kp[i] = b4 ? s[i + 4] : s[i]; }
#pragma unroll
    for (int i = 0; i < 4; i++) kp[i] += __shfl_xor_sync(0xffffffffu, snd[i], 4);
    bool b2 = (c & 2) != 0;
    float k2[2], s2[2];
#pragma unroll
    for (int i = 0; i < 2; i++) { s2[i] = b2 ? kp[i] : kp[i + 2]; k2[i] = b2 ? kp[i + 2] : kp[i]; }
#pragma unroll
    for (int i = 0; i < 2; i++) k2[i] += __shfl_xor_sync(0xffffffffu, s2[i], 2);
    bool b1 = (c & 1) != 0;
    float s1 = b1 ? k2[0] : k2[1];
    float k1 = b1 ? k2[1] : k2[0];
    return k1 + __shfl_xor_sync(0xffffffffu, s1, 1);
}

// Copy the tensormap (by-value launch param) into global memory.
__global__ void k_setup(const __grid_constant__ CUtensorMap tm) {
    const ull* s = (const ull*)&tm;
    if (threadIdx.x < 16) g_tmap[threadIdx.x] = s[threadIdx.x];
}

// ============================ TMA main kernel ============================
// Persistent: 444 CTAs x 256 threads (3/SM). 64-row units via global tickets.
// W: double-buffered 16KB PAIRS, one TMA bulk tensor load each (box 64x64).
// Per pair: 1 mbar_wait + 1 __syncthreads; produce pair p+2 into the buffer
// freed by pair p AFTER the sync — full barriers only, producer never waits,
// no deadlock possible (proven structure from R14, at 2x coarser grain).
// Smem pair layout: 64 rows x 256B; each quarter-warp phase reads a contiguous
// 128B -> conflict-free LDS.128, no W swizzle.
// h in smem, XOR-swizzled; the swizzle term reduces to XOR with c.
__global__ void __launch_bounds__(256, 3) k_main(const float* __restrict__ lhs,
                                                 const float* __restrict__ bias,
                                                 const void* __restrict__ pts_raw,
                                                 float* __restrict__ out) {
    extern __shared__ __align__(128) char smem[];
    float* hs = (float*)(smem + SM_HS);
    float* sblk = (float*)(smem + SM_SBLK);
    int* spts = (int*)(smem + SM_SPTS);
    int* misc = (int*)(smem + SM_MISC);  // [0]=cur ticket, [1]=next ticket, [2]=last flag

    const int tid = threadIdx.x;
    const int warp = tid >> 5, lane = tid & 31;
    const int rgrp = lane >> 3, c = lane & 7;

    const uint32_t smem_u32 = (uint32_t)__cvta_generic_to_shared(smem);
    const uint32_t mb_full = smem_u32 + SM_MBAR;
    // Read slot within a pair-buffer: row_local = warp*8 + q*4 + rgrp,
    // byte = row_local*256 + tt*128 + c*16  (q term = +1024)
    const uint32_t rslot = smem_u32 + SM_W + warp * 2048 + rgrp * 256 + c * 16;
    const void* tmp = (const void*)g_tmap;

    if (tid == 0) {
        mbar_init(mb_full + 0, 1);
        mbar_init(mb_full + 8, 1);
        asm volatile("fence.proxy.async.shared::cta;" ::: "memory");
        misc[0] = (int)atomicAdd(&g_tick, 1u);
        misc[1] = (int)atomicAdd(&g_tick, 1u);
    }

    if (tid < 16) {
        // Detect int64 vs int32 points: values < 4096, so int64 data has all-zero hi words.
        const ull* pw = (const ull*)pts_raw;
        ull h = 0;
#pragma unroll
        for (int i = 0; i < 8; i++) h |= (pw[i] >> 32);
        bool is64 = (h == 0ULL);
        spts[tid] = is64 ? (int)((const long long*)pts_raw)[tid]
                         : ((const int*)pts_raw)[tid];
    }
    sblk[tid] = 0.f;

    // Stage h_last[b][k] = lhs[b, T-1, k] with XOR swizzle on 16B chunks.
#pragma unroll
    for (int i = 0; i < 32; i++) {
        int idx = tid + i * 256;
        int b = idx >> 10, k = idx & 1023;
        int idx16 = k * 2 + (b >> 2);
        int s = idx16 ^ ((idx16 >> 3) & 7);
        hs[s * 4 + (b & 3)] = lhs[b * (TT * DD) + (TT - 1) * DD + k];
    }
    __syncthreads();  // mbarriers + fence + tickets + h visible

    int cur = misc[0];
    int nxt = misc[1];

    const ulonglong2* h8 = (const ulonglong2*)hs;
    int pcnt = 0, ccnt = 0;  // produced / consumed PAIR counters

    // Prologue: produce pairs 0,1 of cur into buffers 0,1
    if (cur < NU) {
        if (tid == 0) {
#pragma unroll
            for (int pp = 0; pp < 2; pp++) {
                mbar_expect_tx(mb_full + pp * 8, PAIR_BYTES);
                tma2d(smem_u32 + SM_W + pp * PAIR_BYTES, tmp, pp * 64, cur * 64,
                      mb_full + pp * 8);
            }
        }
        pcnt = 2;
    }

    while (cur < NU) {
        ull acc[2][4] = {};

        for (int p = 0; p < 16; p++) {
            // Consume pair (global index ccnt)
            int buf = ccnt & 1;
            int par = (ccnt >> 1) & 1;
            ccnt++;
            mbar_wait(mb_full + buf * 8, par);

            uint32_t pb = rslot + buf * PAIR_BYTES;
#pragma unroll
            for (int tt = 0; tt < 2; tt++) {
                int t = p * 2 + tt;
                uint32_t rb = pb + tt * 128;
                float4 w[2];
                asm volatile("ld.shared.v4.f32 {%0,%1,%2,%3}, [%4];"
                             : "=f"(w[0].x), "=f"(w[0].y), "=f"(w[0].z), "=f"(w[0].w)
                             : "r"(rb));
                asm volatile("ld.shared.v4.f32 {%0,%1,%2,%3}, [%4];"
                             : "=f"(w[1].x), "=f"(w[1].y), "=f"(w[1].z), "=f"(w[1].w)
                             : "r"(rb + 1024));

                // h addresses: base has low-3 bits clear; swizzle reduces to XOR with c.
                const ulonglong2* hb = h8 + t * 64 + c * 8;
#define STEP(comp, kk)                                                        \
    do {                                                                      \
        ulonglong2 hA = hb[(2 * (kk)) ^ c];     /* batches 0-3 */             \
        ulonglong2 hB = hb[(2 * (kk) + 1) ^ c]; /* batches 4-7 */             \
        ull wd0 = packw(w[0].comp);                                           \
        fma2(acc[0][0], wd0, hA.x); fma2(acc[0][1], wd0, hA.y);               \
        fma2(acc[0][2], wd0, hB.x); fma2(acc[0][3], wd0, hB.y);               \
        ull wd1 = packw(w[1].comp);                                           \
        fma2(acc[1][0], wd1, hA.x); fma2(acc[1][1], wd1, hA.y);               \
        fma2(acc[1][2], wd1, hB.x); fma2(acc[1][3], wd1, hB.y);               \
    } while (0)
                STEP(x, 0);
                STEP(y, 1);
                STEP(z, 2);
                STEP(w, 3);
#undef STEP
            }

            __syncthreads();  // pair fully consumed by ALL warps -> buffer reusable

            // Produce pair p+2 into the buffer just freed
            int fp = p + 2;
            int punit = (fp < 16) ? cur : nxt;
            int ppair = (fp < 16) ? fp : fp - 16;
            if (punit < NU) {
                if (tid == 0) {
                    int pbuf = pcnt & 1;
                    mbar_expect_tx(mb_full + pbuf * 8, PAIR_BYTES);
                    tma2d(smem_u32 + SM_W + pbuf * PAIR_BYTES, tmp, ppair * 64,
                          punit * 64, mb_full + pbuf * 8);
                }
                pcnt++;
            }
        }

        // Unit epilogue: reduce-scatter (lane c ends with batch c), exp, accumulate.
        int hidx = cur >> 10;  // (cur*64) >> 16
#pragma unroll
        for (int q = 0; q < 2; q++) {
            float s[8];
#pragma unroll
            for (int pp = 0; pp < 4; pp++) {
                s[2 * pp] = lo32(acc[q][pp]);
                s[2 * pp + 1] = hi32(acc[q][pp]);
            }
            float tot = rscatter8(s, c);
            int g = cur * 64 + warp * 8 + q * 4 + rgrp;
            float ev = expf(tot + __ldg(&bias[g]));
            int r = g & (RR - 1);
            atomicAdd(&sblk[hidx * 128 + r * 8 + c], ev);
            int v = (g >> 4) & (VV - 1);
            if (v == spts[c * 2 + hidx]) g_E[c * 32 + hidx * 16 + r] = ev;
        }

        // Advance: cur <- nxt (its first pairs are already in flight), grab a new nxt.
        cur = nxt;
        if (cur < NU) {
            if (tid == 0) misc[1] = (int)atomicAdd(&g_tick, 1u);
            __syncthreads();
            nxt = misc[1];
        }
    }

    __syncthreads(); // all unit epilogues' sblk atomics done
    atomicAdd(&g_S[tid], sblk[tid]);  // tid in [0,256): one red per slot per CTA
    __threadfence();
    __syncthreads();
    if (tid == 0) {
        unsigned o = atomicAdd(&g_fin, 1u);
        misc[2] = (o == (unsigned)(NCTA - 1));
    }
    __syncthreads();

    if (misc[2]) {
        __threadfence();  // acquire: all CTAs' g_S reds visible
        if (tid < 8) {
            float n = 0.f, p = 0.f;
#pragma unroll
            for (int rr = 0; rr < 16; rr++) {
                n += g_S[rr * 8 + tid] * g_S[128 + rr * 8 + tid];
                p += g_E[tid * 32 + rr] * g_E[tid * 32 + 16 + rr];
            }
            out[tid] = p;       // p_eval
            out[8 + tid] = n;   // norm_const
        }
        __syncthreads();  // outputs written before scratch reset
        g_S[tid] = 0.f;   // reset for next graph replay
        if (tid == 0) { g_tick = 0; g_fin = 0; }
    }
}

// ====================== Fallback: proven cp.async kernel ======================
#define STAGES 4
#define STAGE_BYTES 8192
__global__ void __launch_bounds__(256, 3) k_fb(const float* __restrict__ lhs,
                                               const float* __restrict__ Wm,
                                               const float* __restrict__ bias,
                                               const void* __restrict__ pts_raw,
                                               float* __restrict__ out) {
    extern __shared__ __align__(128) char smem[];
    float* hs = (float*)(smem + SM_HS);
    float* sblk = (float*)(smem + SM_SBLK);
    int* spts = (int*)(smem + SM_SPTS);
    int* misc = (int*)(smem + SM_MISC);

    const int tid = threadIdx.x;
    const int warp = tid >> 5, lane = tid & 31;
    const int rgrp = lane >> 3, c = lane & 7;

    const uint32_t smem_u32 = (uint32_t)__cvta_generic_to_shared(smem);
    const uint32_t wbase = smem_u32 + SM_W + warp * 1024 + lane * 16;

    if (tid < 16) {
        const ull* pw = (const ull*)pts_raw;
        ull h = 0;
#pragma unroll
        for (int i = 0; i < 8; i++) h |= (pw[i] >> 32);
        bool is64 = (h == 0ULL);
        spts[tid] = is64 ? (int)((const long long*)pts_raw)[tid]
                         : ((const int*)pts_raw)[tid];
    }
    sblk[tid] = 0.f;

#pragma unroll
    for (int i = 0; i < 32; i++) {
        int idx = tid + i * 256;
        int b = idx >> 10, k = idx & 1023;
        int idx16 = k * 2 + (b >> 2);
        int s = idx16 ^ ((idx16 >> 3) & 7);
        hs[s * 4 + (b & 3)] = lhs[b * (TT * DD) + (TT - 1) * DD + k];
    }

    if (tid == 0) {
        misc[0] = (int)atomicAdd(&g_tick, 1u);
        misc[1] = (int)atomicAdd(&g_tick, 1u);
    }
    __syncthreads();
    int cur = misc[0];
    int nxt = misc[1];

    const ulonglong2* h8 = (const ulonglong2*)hs;
    int swrite = STAGES - 1, sread = 0;

    if (cur < NU) {
        const float* g0 = Wm + (size_t)(cur * 64 + warp * 8 + rgrp) * 1024 + c * 4;
#pragma unroll
        for (int t = 0; t < STAGES - 1; t++) {
            uint32_t d = wbase + t * STAGE_BYTES;
            cp16(d, g0 + t * 32);
            cp16(d + 512, g0 + 4096 + t * 32);
            cp_commit();
        }
    } else {
#pragma unroll
        for (int t = 0; t < STAGES - 1; t++) cp_commit();
    }

    while (cur < NU) {
        const float* gc = Wm + (size_t)(cur * 64 + warp * 8 + rgrp) * 1024 + c * 4;
        const float* gn = (nxt < NU)
                              ? Wm + (size_t)(nxt * 64 + warp * 8 + rgrp) * 1024 + c * 4
                              : (const float*)0;

        ull acc[2][4] = {};

        for (int t = 0; t < 32; t++) {
            cp_wait2();
            {
                int ft = t + (STAGES - 1);
                uint32_t d = wbase + swrite * STAGE_BYTES;
                if (ft < 32) {
                    cp16(d, gc + ft * 32);
                    cp16(d + 512, gc + 4096 + ft * 32);
                } else if (gn) {
                    int f2 = ft - 32;
                    cp16(d, gn + f2 * 32);
                    cp16(d + 512, gn + 4096 + f2 * 32);
                }
                cp_commit();
                swrite++; if (swrite == STAGES) swrite = 0;
            }

            uint32_t s = wbase + sread * STAGE_BYTES;
            sread++; if (sread == STAGES) sread = 0;
            float4 w[2];
            asm volatile("ld.shared.v4.f32 {%0,%1,%2,%3}, [%4];"
                         : "=f"(w[0].x), "=f"(w[0].y), "=f"(w[0].z), "=f"(w[0].w)
                         : "r"(s));
            asm volatile("ld.shared.v4.f32 {%0,%1,%2,%3}, [%4];"
                         : "=f"(w[1].x), "=f"(w[1].y), "=f"(w[1].z), "=f"(w[1].w)
                         : "r"(s + 512));

            const ulonglong2* hb = h8 + t * 64 + c * 8;
#define STEP(comp, kk)                                                        \
    do {                                                                      \
        ulonglong2 hA = hb[(2 * (kk)) ^ c];                                   \
        ulonglong2 hB = hb[(2 * (kk) + 1) ^ c];                               \
        ull wd0 = packw(w[0].comp);                                           \
        fma2(acc[0][0], wd0, hA.x); fma2(acc[0][1], wd0, hA.y);               \
        fma2(acc[0][2], wd0, hB.x); fma2(acc[0][3], wd0, hB.y);               \
        ull wd1 = packw(w[1].comp);                                           \
        fma2(acc[1][0], wd1, hA.x); fma2(acc[1][1], wd1, hA.y);               \
        fma2(acc[1][2], wd1, hB.x); fma2(acc[1][3], wd1, hB.y);               \
    } while (0)
            STEP(x, 0);
            STEP(y, 1);
            STEP(z, 2);
            STEP(w, 3);
#undef STEP
        }

        int hidx = cur >> 10;
#pragma unroll
        for (int q = 0; q < 2; q++) {
            float s[8];
#pragma unroll
            for (int pp = 0; pp < 4; pp++) {
                s[2 * pp] = lo32(acc[q][pp]);
                s[2 * pp + 1] = hi32(acc[q][pp]);
            }
            float tot = rscatter8(s, c);
            int g = cur * 64 + warp * 8 + q * 4 + rgrp;
            float ev = expf(tot + __ldg(&bias[g]));
            int r = g & (RR - 1);
            atomicAdd(&sblk[hidx * 128 + r * 8 + c], ev);
            int v = (g >> 4) & (VV - 1);
            if (v == spts[c * 2 + hidx]) g_E[c * 32 + hidx * 16 + r] = ev;
        }

        cur = nxt;
        if (cur < NU) {
            if (tid == 0) misc[1] = (int)atomicAdd(&g_tick, 1u);
            __syncthreads();
            nxt = misc[1];
        }
    }

    cp_waitall();
    __syncthreads();
    atomicAdd(&g_S[tid], sblk[tid]);
    __threadfence();
    __syncthreads();
    if (tid == 0) {
        unsigned o = atomicAdd(&g_fin, 1u);
        misc[2] = (o == (unsigned)(NCTA - 1));
    }
    __syncthreads();

    if (misc[2]) {
        __threadfence();
        if (tid < 8) {
            float n = 0.f, p = 0.f;
#pragma unroll
            for (int rr = 0; rr < 16; rr++) {
                n += g_S[rr * 8 + tid] * g_S[128 + rr * 8 + tid];
                p += g_E[tid * 32 + rr] * g_E[tid * 32 + 16 + rr];
            }
            out[tid] = p;
            out[8 + tid] = n;
        }
        __syncthreads();
        g_S[tid] = 0.f;
        if (tid == 0) { g_tick = 0; g_fin = 0; }
    }
}

// ---- Host side ----
typedef CUresult (*tmap_encode_fn)(CUtensorMap*, CUtensorMapDataType, cuuint32_t, void*,
                                   const cuuint64_t*, const cuuint64_t*, const cuuint32_t*,
                                   const cuuint32_t*, CUtensorMapInterleave, CUtensorMapSwizzle,
                                   CUtensorMapL2promotion, CUtensorMapFloatOOBfill);

extern "C" void kernel_launch(void* const* d_in, const int* in_sizes, int n_in,
                              void* d_out, int out_size) {
    const float* lhs = nullptr;
    const float* Wm = nullptr;
    const float* bias = nullptr;
    const void* pts = nullptr;
    for (int i = 0; i < n_in; i++) {
        int sz = in_sizes[i];
        if (sz == GG * DD) Wm = (const float*)d_in[i];
        else if (sz == BB * TT * DD) lhs = (const float*)d_in[i];
        else if (sz == GG) bias = (const float*)d_in[i];
        else if (sz == BB * HH) pts = d_in[i];
    }
    if (!lhs) lhs = (const float*)d_in[0];
    if (!Wm) Wm = (const float*)d_in[1];
    if (!bias) bias = (const float*)d_in[2];
    if (!pts) pts = d_in[3];

    static int mode = -1;  // 0 = TMA path, 1 = cp.async fallback
    static CUtensorMap tmap;
    if (mode < 0) {
        mode = 1;
        void* p = nullptr;
        cudaDriverEntryPointQueryResult qr = cudaDriverEntryPointSymbolNotFound;
        cudaError_t ce = cudaGetDriverEntryPointByVersion("cuTensorMapEncodeTiled", &p,
                                                          12000, cudaEnableDefault, &qr);
        if (ce == cudaSuccess && p && qr == cudaDriverEntryPointSuccess) {
            tmap_encode_fn tfn = (tmap_encode_fn)p;
            cuuint64_t dims[2] = {(cuuint64_t)DD, (cuuint64_t)GG};
            cuuint64_t strides[1] = {(cuuint64_t)DD * sizeof(float)};
            cuuint32_t box[2] = {64, 64};  // one 16KB pair per TMA
            cuuint32_t estr[2] = {1, 1};
            CUresult cr = tfn(&tmap, CU_TENSOR_MAP_DATA_TYPE_FLOAT32, 2, (void*)Wm, dims,
                              strides, box, estr, CU_TENSOR_MAP_INTERLEAVE_NONE,
                              CU_TENSOR_MAP_SWIZZLE_NONE, CU_TENSOR_MAP_L2_PROMOTION_L2_128B,
                              CU_TENSOR_MAP_FLOAT_OOB_FILL_NONE);
            if (cr == CUDA_SUCCESS) mode = 0;
        }
        cudaFuncSetAttribute(k_main, cudaFuncAttributeMaxDynamicSharedMemorySize, SMEM_TOTAL);
        cudaFuncSetAttribute(k_fb, cudaFuncAttributeMaxDynamicSharedMemorySize, SMEM_TOTAL);
    }

    if (mode == 0) {
        k_setup<<<1, 16>>>(tmap);
        k_main<<<NCTA, 256, SMEM_TOTAL>>>(lhs, bias, pts, (float*)d_out);
    } else {
        k_fb<<<NCTA, 256, SMEM_TOTAL>>>(lhs, Wm, bias, pts, (float*)d_out);
    }
}